// round 14
// baseline (speedup 1.0000x reference)
#include <cuda_runtime.h>
#include <cstdint>

#define Bn 16
#define Nn 1024
#define Dn 512
#define Fn 257
#define FP 272            // padded to multiple of 16 for gram k-chunks
#define NROW (Bn*Nn)

typedef unsigned long long ull;

// ---------------- scratch (static device globals; no allocation) ----------------
__device__ float    g_w[FP];
__device__ float    g_twg[512];                    // (float)cos(2pi k/512), filled once
__device__ float    g_Y[(size_t)NROW * FP];        // ~17.8 MB
__device__ float    g_sq[NROW];
__device__ unsigned g_minbits[NROW];               // float bits of row-min dist (j != i)
__device__ float    g_dist[(size_t)NROW * Nn];     // 64 MB

// ---------------- packed f32x2 helpers (per-lane IEEE fp32, bit-identical) ----------
__device__ __forceinline__ ull pk2(float lo, float hi) {
    ull r;
    asm("mov.b64 %0, {%1, %2};" : "=l"(r) : "f"(lo), "f"(hi));
    return r;
}
__device__ __forceinline__ void upk2(ull v, float& lo, float& hi) {
    asm("mov.b64 {%0, %1}, %2;" : "=f"(lo), "=f"(hi) : "l"(v));
}
__device__ __forceinline__ void fma2(ull& d, ull a, ull b) {
    asm("fma.rn.f32x2 %0, %1, %2, %0;" : "+l"(d) : "l"(a), "l"(b));
}

// ---------------- exact-rounding helper (DFT only) ----------------
__device__ __forceinline__ void two_sum(float a, float b, float& s, float& e) {
    s = __fadd_rn(a, b);
    float bb = __fsub_rn(s, a);
    e = __fadd_rn(__fsub_rn(a, __fsub_rn(s, bb)), __fsub_rn(b, bb));
}

// ---------------- K0: w = rowsum(A); twiddle table; init row mins ----------------
__global__ void k_init(const float* __restrict__ A) {
    int t = blockIdx.x * blockDim.x + threadIdx.x;
    if (t < NROW) g_minbits[t] = 0x7F800000u;  // +inf
    if (t < 512) {
        double ang = (2.0 * 3.141592653589793238 / 512.0) * (double)t;
        g_twg[t] = (float)cos(ang);            // same value bits as before
    }
    int w = t >> 5, lane = t & 31;
    if (w < FP) {
        float s = 0.f;
        if (w < Fn) {
            for (int j = lane; j < Fn; j += 32) s = __fadd_rn(s, A[w * Fn + j]);
        }
#pragma unroll
        for (int o = 16; o; o >>= 1) s = __fadd_rn(s, __shfl_down_sync(0xFFFFFFFFu, s, o));
        if (lane == 0) g_w[w] = s;   // padded rows (w>=Fn) write 0
    }
}

// ---------------- K1: Y[row][f] = |DFT_f(x_row)| * w[f], compensated ----------------
// round-11 version verbatim (best measured)
#define DFT_ROWS 4
__global__ void __launch_bounds__(288) k_dft(const float* __restrict__ X) {
    __shared__ float tw[512];
    __shared__ float xs[DFT_ROWS][512];
    int tid = threadIdx.x;
    for (int k = tid; k < 512; k += 288) tw[k] = g_twg[k];
    int row0 = blockIdx.x * DFT_ROWS;
    const float* Xp = X + (size_t)row0 * Dn;
    for (int i = tid; i < DFT_ROWS * Dn; i += 288) xs[i >> 9][i & 511] = Xp[i];
    __syncthreads();

    int f = tid;
    if (f < Fn) {
        float rs[DFT_ROWS], re_[DFT_ROWS], is_[DFT_ROWS], ie_[DFT_ROWS];
#pragma unroll
        for (int r = 0; r < DFT_ROWS; r++) { rs[r] = 0.f; re_[r] = 0.f; is_[r] = 0.f; ie_[r] = 0.f; }
        int k = 0;
        for (int ch = 0; ch < 32; ch++) {            // 32 chunks of 16 samples
            float rc[DFT_ROWS], ic[DFT_ROWS];
#pragma unroll
            for (int r = 0; r < DFT_ROWS; r++) { rc[r] = 0.f; ic[r] = 0.f; }
#pragma unroll
            for (int d4 = 0; d4 < 4; d4++) {
                int dbase = ch * 16 + d4 * 4;
                float4 xv[DFT_ROWS];
#pragma unroll
                for (int r = 0; r < DFT_ROWS; r++) xv[r] = *(const float4*)&xs[r][dbase];
#pragma unroll
                for (int dd = 0; dd < 4; dd++) {
                    float c = tw[k];
                    float s = tw[(k + 128) & 511];   // == -sin (sign irrelevant for |.|)
#pragma unroll
                    for (int r = 0; r < DFT_ROWS; r++) {
                        float x = (dd == 0) ? xv[r].x : (dd == 1) ? xv[r].y : (dd == 2) ? xv[r].z : xv[r].w;
                        rc[r] = fmaf(x, c, rc[r]);
                        ic[r] = fmaf(x, s, ic[r]);
                    }
                    k = (k + f) & 511;
                }
            }
            // TwoSum-fold chunk partials into compensated accumulators
#pragma unroll
            for (int r = 0; r < DFT_ROWS; r++) {
                float s, e;
                two_sum(rs[r], rc[r], s, e);  rs[r]  = s; re_[r] = __fadd_rn(re_[r], e);
                two_sum(is_[r], ic[r], s, e); is_[r] = s; ie_[r] = __fadd_rn(ie_[r], e);
            }
        }
        float wf = g_w[f];
#pragma unroll
        for (int r = 0; r < DFT_ROWS; r++) {
            // float-float magnitude: (rs+re)^2 + (is+ie)^2, refined sqrt
            float hr = __fmul_rn(rs[r], rs[r]);
            float lr = fmaf(rs[r], rs[r], -hr);
            float hi = __fmul_rn(is_[r], is_[r]);
            float li = fmaf(is_[r], is_[r], -hi);
            float S, E;
            two_sum(hr, hi, S, E);
            float cross2 = __fadd_rn(__fmul_rn(2.0f, __fmul_rn(rs[r], re_[r])),
                                     __fmul_rn(2.0f, __fmul_rn(is_[r], ie_[r])));
            E = __fadd_rn(E, __fadd_rn(__fadd_rn(lr, li), cross2));
            float rt = __fsqrt_rn(S);
            float resid = __fadd_rn(fmaf(-rt, rt, S), E);
            float mag = fmaf(resid, __fdiv_rn(0.5f, rt), rt);
            if (S == 0.0f) mag = 0.0f;
            g_Y[(size_t)(row0 + r) * FP + f] = __fmul_rn(mag, wf);
        }
    } else if (f < FP) {
        for (int r = 0; r < DFT_ROWS; r++) g_Y[(size_t)(row0 + r) * FP + f] = 0.f;
    }
}

// ---------------- K1b: sq[row] = sum_f Y^2 — XLA row-reduce mimicry ----------------
__global__ void __launch_bounds__(256) k_sq() {
    int row = blockIdx.x * 8 + (threadIdx.x >> 5);
    int lane = threadIdx.x & 31;
    const float* Yp = g_Y + (size_t)row * FP;
    float s = 0.f;
    for (int f = lane; f < Fn; f += 32) {
        float y = Yp[f];
        s = __fadd_rn(s, __fmul_rn(y, y));   // mul then add, NOT fma
    }
#pragma unroll
    for (int o = 16; o; o >>= 1) s = __fadd_rn(s, __shfl_down_sync(0xFFFFFFFFu, s, o));
    if (lane == 0) g_sq[row] = s;
}

// ---------------- K2: Gram -> dist + row-min, FFMA2 (register-only packing) ---------
// smem layout + loads identical to the 216us scalar version; only the per-kk
// register math changes: a duplicated to (a,a) pairs, b pairs from float4 regs,
// 32x fma.rn.f32x2 replaces 64x FFMA. Same sequential chain per lane ->
// bit-identical dist.
__global__ void __launch_bounds__(256) k_gram() {
    __shared__ float As[16][132];
    __shared__ float Bs[16][132];
    int b = blockIdx.z;
    int i0 = blockIdx.y * 128, j0 = blockIdx.x * 128;
    const float* Yb = g_Y + (size_t)b * Nn * FP;
    int tid = threadIdx.x;
    int tx = tid & 15, ty = tid >> 4;
    ull accP[8][4];
#pragma unroll
    for (int q = 0; q < 8; q++)
#pragma unroll
        for (int w = 0; w < 4; w++) accP[q][w] = 0ull;

    for (int k0 = 0; k0 < FP; k0 += 16) {
#pragma unroll
        for (int q = 0; q < 2; q++) {
            int idx = tid + q * 256;       // 0..511
            int i   = idx >> 2;            // tile row 0..127
            int k4  = (idx & 3) << 2;      // 0,4,8,12
            float4 va = *(const float4*)&Yb[(size_t)(i0 + i) * FP + k0 + k4];
            As[k4 + 0][i] = va.x; As[k4 + 1][i] = va.y; As[k4 + 2][i] = va.z; As[k4 + 3][i] = va.w;
            float4 vb = *(const float4*)&Yb[(size_t)(j0 + i) * FP + k0 + k4];
            Bs[k4 + 0][i] = vb.x; Bs[k4 + 1][i] = vb.y; Bs[k4 + 2][i] = vb.z; Bs[k4 + 3][i] = vb.w;
        }
        __syncthreads();
#pragma unroll
        for (int kk = 0; kk < 16; kk++) {
            float av[8];
            *(float4*)&av[0] = *(const float4*)&As[kk][ty * 8];
            *(float4*)&av[4] = *(const float4*)&As[kk][ty * 8 + 4];
            float4 b0 = *(const float4*)&Bs[kk][tx * 8];
            float4 b1 = *(const float4*)&Bs[kk][tx * 8 + 4];
            ull bp[4] = { pk2(b0.x, b0.y), pk2(b0.z, b0.w),
                          pk2(b1.x, b1.y), pk2(b1.z, b1.w) };
#pragma unroll
            for (int q = 0; q < 8; q++) {
                ull aq = pk2(av[q], av[q]);        // register dup, alu pipe
#pragma unroll
                for (int w = 0; w < 4; w++) fma2(accP[q][w], aq, bp[w]);
            }
        }
        __syncthreads();
    }

    // unpack to scalars; epilogue identical to the passing scalar version
    float acc[8][8];
#pragma unroll
    for (int q = 0; q < 8; q++)
#pragma unroll
        for (int w = 0; w < 4; w++) upk2(accP[q][w], acc[q][2 * w], acc[q][2 * w + 1]);

    float sqi[8], sqj[8], rmin[8];
#pragma unroll
    for (int q = 0; q < 8; q++) { sqi[q] = g_sq[b * Nn + i0 + ty * 8 + q]; rmin[q] = 3.0e38f; }
#pragma unroll
    for (int w = 0; w < 8; w++) sqj[w] = g_sq[b * Nn + j0 + tx * 8 + w];

    float* distp = g_dist + (size_t)b * Nn * Nn;
#pragma unroll
    for (int q = 0; q < 8; q++) {
        int i = i0 + ty * 8 + q;
        float dl[8];
#pragma unroll
        for (int w = 0; w < 8; w++) {
            int j = j0 + tx * 8 + w;
            // ref op order: (sq_i + sq_j) - 2*cross, then max(.,0), no FMA
            float t = __fadd_rn(sqi[q], sqj[w]);
            float d = fmaxf(__fsub_rn(t, __fmul_rn(2.0f, acc[q][w])), 0.f);
            dl[w] = d;
            if (i != j) rmin[q] = fminf(rmin[q], d);
        }
        *(float4*)(distp + (size_t)i * Nn + j0 + tx * 8)     = make_float4(dl[0], dl[1], dl[2], dl[3]);
        *(float4*)(distp + (size_t)i * Nn + j0 + tx * 8 + 4) = make_float4(dl[4], dl[5], dl[6], dl[7]);
    }
#pragma unroll
    for (int q = 0; q < 8; q++) {
        float m = rmin[q];
#pragma unroll
        for (int o = 8; o; o >>= 1) m = fminf(m, __shfl_down_sync(0xFFFFFFFFu, m, o, 16));
        if (tx == 0) atomicMin(&g_minbits[b * Nn + i0 + ty * 8 + q], __float_as_uint(m));
    }
}

// ---------------- threefry2x32 (JAX partitionable random_bits, 32-bit) ----------------
__device__ __forceinline__ unsigned tf_bits(unsigned lo) {
    const unsigned k0 = 0u, k1 = 42u, k2 = 0x1BD11BDAu ^ 0u ^ 42u;
    unsigned x0 = 0u + k0;      // hi32 of uint64 iota index is 0 for this size
    unsigned x1 = lo + k1;
#define RND(r) { x0 += x1; x1 = __funnelshift_l(x1, x1, (r)); x1 ^= x0; }
    RND(13) RND(15) RND(26) RND(6)   x0 += k1; x1 += k2 + 1u;
    RND(17) RND(29) RND(16) RND(24)  x0 += k2; x1 += k0 + 2u;
    RND(13) RND(15) RND(26) RND(6)   x0 += k0; x1 += k1 + 3u;
    RND(17) RND(29) RND(16) RND(24)  x0 += k1; x1 += k2 + 4u;
    RND(13) RND(15) RND(26) RND(6)   x0 += k2; x1 += k0 + 5u;
#undef RND
    return x0 ^ x1;   // 32-bit partitionable: xor of the two output words
}

// accurate fp32 ln (immune to -use_fast_math), ~1-2 ulp on [2^-126, 2)
__device__ __forceinline__ float alogf(float x) {
    int i = __float_as_int(x);
    int e = ((i >> 23) & 0xFF) - 127;
    float m = __int_as_float((i & 0x007FFFFF) | 0x3F800000);
    if (m > 1.41421356f) { m *= 0.5f; e += 1; }
    float t = m - 1.0f;
    float s = __fdiv_rn(t, t + 2.0f);
    float z = s * s;
    float poly = fmaf(z, fmaf(z, fmaf(z, 0.14285715f, 0.2f), 0.33333334f), 1.0f);
    float lnm = 2.0f * s * poly;
    float ef = (float)e;
    return fmaf(ef, 0.693359375f, fmaf(ef, -2.12194440e-4f, lnm));
}

__device__ __forceinline__ float neg_log_u(unsigned bits) {
    float u = __uint_as_float((bits >> 9) | 0x3F800000u) - 1.0f;
    u = fmaxf(u, 1.17549435e-38f);   // bitwise-equal to JAX's minval clamp
    return -alogf(u);                // a = -ln u > 0
}

// ---------------- K3: gumbel-bernoulli mask ----------------
// decision: p^2 * a1 >= (1-p)^2 * a0; fp32 fast path + guard band, fp64 fallback.
__global__ void __launch_bounds__(256) k_mask(float* __restrict__ out) {
    int g = blockIdx.x * blockDim.x + threadIdx.x;   // 4M threads, 4 cols each
    int c0 = (g & 255) << 2;
    int r  = (g >> 8) & 1023;
    int b  = g >> 18;
    size_t rowbase = ((size_t)b * Nn + r) * Nn;
    float4 dv = *(const float4*)(g_dist + rowbase + c0);
    float dmin  = __uint_as_float(g_minbits[b * Nn + r]);
    float emax  = __fdiv_rn(1.0f, __fadd_rn(dmin, 1e-10f));
    float emaxp = __fadd_rn(emax, 1e-10f);
    float dd[4] = {dv.x, dv.y, dv.z, dv.w};
    unsigned lbase = ((unsigned)(b * Nn + r) * (unsigned)Nn + (unsigned)c0) * 2u;
    float res[4];
#pragma unroll
    for (int q = 0; q < 4; q++) {
        int c = c0 + q;
        float p;
        if (c == r) {
            p = 0.01f;
        } else {
            float ed = __fdiv_rn(1.0f, __fadd_rn(dd[q], 1e-10f));
            p = __fmul_rn(__fdiv_rn(ed, emaxp), 0.99f);
        }
        float a0 = neg_log_u(tf_bits(lbase + 2u * (unsigned)q));
        float a1 = neg_log_u(tf_bits(lbase + 2u * (unsigned)q + 1u));
        float om = __fsub_rn(1.0f, p);
        float t1 = __fmul_rn(__fmul_rn(p,  p),  a1);
        float t0 = __fmul_rn(__fmul_rn(om, om), a0);
        float diff = __fsub_rn(t1, t0);
        if (fabsf(diff) > __fmul_rn(4e-7f, __fadd_rn(t1, t0))) {
            res[q] = (diff >= 0.0f) ? 1.0f : 0.0f;   // fp32 sign provably == fp64 sign
        } else {
            double pd = (double)p;
            double omd = 1.0 - pd;
            res[q] = (pd * pd * (double)a1 >= omd * omd * (double)a0) ? 1.0f : 0.0f;
        }
    }
    *(float4*)(out + rowbase + c0) = make_float4(res[0], res[1], res[2], res[3]);
}

// ---------------- launch ----------------
extern "C" void kernel_launch(void* const* d_in, const int* in_sizes, int n_in,
                              void* d_out, int out_size) {
    const float* X = (const float*)d_in[0];
    const float* A = (const float*)d_in[1];
    float* out = (float*)d_out;

    k_init<<<64, 256>>>(A);
    k_dft<<<NROW / DFT_ROWS, 288>>>(X);
    k_sq<<<NROW / 8, 256>>>();
    dim3 gg(Nn / 128, Nn / 128, Bn);
    k_gram<<<gg, 256>>>();
    k_mask<<<(Bn * Nn * (Nn / 4)) / 256, 256>>>(out);
}

// round 15
// speedup vs baseline: 1.5385x; 1.5385x over previous
#include <cuda_runtime.h>
#include <cstdint>

#define Bn 16
#define Nn 1024
#define Dn 512
#define Fn 257
#define FP 272            // padded to multiple of 16 for gram k-chunks
#define NROW (Bn*Nn)

// ---------------- scratch (static device globals; no allocation) ----------------
__device__ float    g_w[FP];
__device__ float    g_twg[512];                    // (float)cos(2pi k/512), filled once
__device__ float    g_Y[(size_t)NROW * FP];        // ~17.8 MB
__device__ float    g_sq[NROW];
__device__ unsigned g_minbits[NROW];               // float bits of row-min dist (j != i)
__device__ float    g_dist[(size_t)NROW * Nn];     // 64 MB

// ---------------- exact-rounding helper (DFT only) ----------------
__device__ __forceinline__ void two_sum(float a, float b, float& s, float& e) {
    s = __fadd_rn(a, b);
    float bb = __fsub_rn(s, a);
    e = __fadd_rn(__fsub_rn(a, __fsub_rn(s, bb)), __fsub_rn(b, bb));
}

// ---------------- K0: w = rowsum(A); twiddle table; init row mins ----------------
__global__ void k_init(const float* __restrict__ A) {
    int t = blockIdx.x * blockDim.x + threadIdx.x;
    if (t < NROW) g_minbits[t] = 0x7F800000u;  // +inf
    if (t < 512) {
        double ang = (2.0 * 3.141592653589793238 / 512.0) * (double)t;
        g_twg[t] = (float)cos(ang);            // same value bits as before
    }
    int w = t >> 5, lane = t & 31;
    if (w < FP) {
        float s = 0.f;
        if (w < Fn) {
            for (int j = lane; j < Fn; j += 32) s = __fadd_rn(s, A[w * Fn + j]);
        }
#pragma unroll
        for (int o = 16; o; o >>= 1) s = __fadd_rn(s, __shfl_down_sync(0xFFFFFFFFu, s, o));
        if (lane == 0) g_w[w] = s;   // padded rows (w>=Fn) write 0
    }
}

// ---------------- K1: Y[row][f] = |DFT_f(x_row)| * w[f], compensated -----------
// round-11 DFT body verbatim; afterwards warps 0-3 compute sq[row] with the
// EXACT k_sq loop (lane-strided f, mul-then-add, shfl-down tree) from smem.
#define DFT_ROWS 4
__global__ void __launch_bounds__(288) k_dft(const float* __restrict__ X) {
    __shared__ float tw[512];
    __shared__ float xs[DFT_ROWS][512];
    __shared__ float ys[DFT_ROWS][264];
    int tid = threadIdx.x;
    for (int k = tid; k < 512; k += 288) tw[k] = g_twg[k];
    int row0 = blockIdx.x * DFT_ROWS;
    const float* Xp = X + (size_t)row0 * Dn;
    for (int i = tid; i < DFT_ROWS * Dn; i += 288) xs[i >> 9][i & 511] = Xp[i];
    __syncthreads();

    int f = tid;
    if (f < Fn) {
        float rs[DFT_ROWS], re_[DFT_ROWS], is_[DFT_ROWS], ie_[DFT_ROWS];
#pragma unroll
        for (int r = 0; r < DFT_ROWS; r++) { rs[r] = 0.f; re_[r] = 0.f; is_[r] = 0.f; ie_[r] = 0.f; }
        int k = 0;
        for (int ch = 0; ch < 32; ch++) {            // 32 chunks of 16 samples
            float rc[DFT_ROWS], ic[DFT_ROWS];
#pragma unroll
            for (int r = 0; r < DFT_ROWS; r++) { rc[r] = 0.f; ic[r] = 0.f; }
#pragma unroll
            for (int d4 = 0; d4 < 4; d4++) {
                int dbase = ch * 16 + d4 * 4;
                float4 xv[DFT_ROWS];
#pragma unroll
                for (int r = 0; r < DFT_ROWS; r++) xv[r] = *(const float4*)&xs[r][dbase];
#pragma unroll
                for (int dd = 0; dd < 4; dd++) {
                    float c = tw[k];
                    float s = tw[(k + 128) & 511];   // == -sin (sign irrelevant for |.|)
#pragma unroll
                    for (int r = 0; r < DFT_ROWS; r++) {
                        float x = (dd == 0) ? xv[r].x : (dd == 1) ? xv[r].y : (dd == 2) ? xv[r].z : xv[r].w;
                        rc[r] = fmaf(x, c, rc[r]);
                        ic[r] = fmaf(x, s, ic[r]);
                    }
                    k = (k + f) & 511;
                }
            }
            // TwoSum-fold chunk partials into compensated accumulators
#pragma unroll
            for (int r = 0; r < DFT_ROWS; r++) {
                float s, e;
                two_sum(rs[r], rc[r], s, e);  rs[r]  = s; re_[r] = __fadd_rn(re_[r], e);
                two_sum(is_[r], ic[r], s, e); is_[r] = s; ie_[r] = __fadd_rn(ie_[r], e);
            }
        }
        float wf = g_w[f];
#pragma unroll
        for (int r = 0; r < DFT_ROWS; r++) {
            // float-float magnitude: (rs+re)^2 + (is+ie)^2, refined sqrt
            float hr = __fmul_rn(rs[r], rs[r]);
            float lr = fmaf(rs[r], rs[r], -hr);
            float hi = __fmul_rn(is_[r], is_[r]);
            float li = fmaf(is_[r], is_[r], -hi);
            float S, E;
            two_sum(hr, hi, S, E);
            float cross2 = __fadd_rn(__fmul_rn(2.0f, __fmul_rn(rs[r], re_[r])),
                                     __fmul_rn(2.0f, __fmul_rn(is_[r], ie_[r])));
            E = __fadd_rn(E, __fadd_rn(__fadd_rn(lr, li), cross2));
            float rt = __fsqrt_rn(S);
            float resid = __fadd_rn(fmaf(-rt, rt, S), E);
            float mag = fmaf(resid, __fdiv_rn(0.5f, rt), rt);
            if (S == 0.0f) mag = 0.0f;
            float y = __fmul_rn(mag, wf);
            g_Y[(size_t)(row0 + r) * FP + f] = y;
            ys[r][f] = y;
        }
    } else if (f < FP) {
        for (int r = 0; r < DFT_ROWS; r++) {
            g_Y[(size_t)(row0 + r) * FP + f] = 0.f;
            if (f < 264) ys[r][f] = 0.f;
        }
    }
    __syncthreads();
    // ---- fused k_sq: identical XLA row-reduce per row (warps 0..3) ----
    int wrp = tid >> 5, lane = tid & 31;
    if (wrp < DFT_ROWS) {
        float s = 0.f;
        for (int ff = lane; ff < Fn; ff += 32) {
            float y = ys[wrp][ff];
            s = __fadd_rn(s, __fmul_rn(y, y));   // mul then add, NOT fma
        }
#pragma unroll
        for (int o = 16; o; o >>= 1) s = __fadd_rn(s, __shfl_down_sync(0xFFFFFFFFu, s, o));
        if (lane == 0) g_sq[row0 + wrp] = s;
    }
}

// ---------------- K2: Gram -> dist + row-min (scalar version, at FFMA roofline) -----
__global__ void __launch_bounds__(256) k_gram() {
    __shared__ float As[16][132];
    __shared__ float Bs[16][132];
    int b = blockIdx.z;
    int i0 = blockIdx.y * 128, j0 = blockIdx.x * 128;
    const float* Yb = g_Y + (size_t)b * Nn * FP;
    int tid = threadIdx.x;
    int tx = tid & 15, ty = tid >> 4;
    float acc[8][8];
#pragma unroll
    for (int q = 0; q < 8; q++)
#pragma unroll
        for (int w = 0; w < 8; w++) acc[q][w] = 0.f;

    for (int k0 = 0; k0 < FP; k0 += 16) {
#pragma unroll
        for (int q = 0; q < 2; q++) {
            int idx = tid + q * 256;       // 0..511
            int i   = idx >> 2;            // tile row 0..127
            int k4  = (idx & 3) << 2;      // 0,4,8,12
            float4 va = *(const float4*)&Yb[(size_t)(i0 + i) * FP + k0 + k4];
            As[k4 + 0][i] = va.x; As[k4 + 1][i] = va.y; As[k4 + 2][i] = va.z; As[k4 + 3][i] = va.w;
            float4 vb = *(const float4*)&Yb[(size_t)(j0 + i) * FP + k0 + k4];
            Bs[k4 + 0][i] = vb.x; Bs[k4 + 1][i] = vb.y; Bs[k4 + 2][i] = vb.z; Bs[k4 + 3][i] = vb.w;
        }
        __syncthreads();
#pragma unroll
        for (int kk = 0; kk < 16; kk++) {
            float av[8], bw[8];
            *(float4*)&av[0] = *(const float4*)&As[kk][ty * 8];
            *(float4*)&av[4] = *(const float4*)&As[kk][ty * 8 + 4];
            *(float4*)&bw[0] = *(const float4*)&Bs[kk][tx * 8];
            *(float4*)&bw[4] = *(const float4*)&Bs[kk][tx * 8 + 4];
#pragma unroll
            for (int q = 0; q < 8; q++)
#pragma unroll
                for (int w = 0; w < 8; w++) acc[q][w] = fmaf(av[q], bw[w], acc[q][w]);
        }
        __syncthreads();
    }

    float sqi[8], sqj[8], rmin[8];
#pragma unroll
    for (int q = 0; q < 8; q++) { sqi[q] = g_sq[b * Nn + i0 + ty * 8 + q]; rmin[q] = 3.0e38f; }
#pragma unroll
    for (int w = 0; w < 8; w++) sqj[w] = g_sq[b * Nn + j0 + tx * 8 + w];

    float* distp = g_dist + (size_t)b * Nn * Nn;
#pragma unroll
    for (int q = 0; q < 8; q++) {
        int i = i0 + ty * 8 + q;
        float dl[8];
#pragma unroll
        for (int w = 0; w < 8; w++) {
            int j = j0 + tx * 8 + w;
            // ref op order: (sq_i + sq_j) - 2*cross, then max(.,0), no FMA
            float t = __fadd_rn(sqi[q], sqj[w]);
            float d = fmaxf(__fsub_rn(t, __fmul_rn(2.0f, acc[q][w])), 0.f);
            dl[w] = d;
            if (i != j) rmin[q] = fminf(rmin[q], d);
        }
        *(float4*)(distp + (size_t)i * Nn + j0 + tx * 8)     = make_float4(dl[0], dl[1], dl[2], dl[3]);
        *(float4*)(distp + (size_t)i * Nn + j0 + tx * 8 + 4) = make_float4(dl[4], dl[5], dl[6], dl[7]);
    }
#pragma unroll
    for (int q = 0; q < 8; q++) {
        float m = rmin[q];
#pragma unroll
        for (int o = 8; o; o >>= 1) m = fminf(m, __shfl_down_sync(0xFFFFFFFFu, m, o, 16));
        if (tx == 0) atomicMin(&g_minbits[b * Nn + i0 + ty * 8 + q], __float_as_uint(m));
    }
}

// ---------------- threefry2x32 (JAX partitionable random_bits, 32-bit) ----------------
__device__ __forceinline__ unsigned tf_bits(unsigned lo) {
    const unsigned k0 = 0u, k1 = 42u, k2 = 0x1BD11BDAu ^ 0u ^ 42u;
    unsigned x0 = 0u + k0;      // hi32 of uint64 iota index is 0 for this size
    unsigned x1 = lo + k1;
#define RND(r) { x0 += x1; x1 = __funnelshift_l(x1, x1, (r)); x1 ^= x0; }
    RND(13) RND(15) RND(26) RND(6)   x0 += k1; x1 += k2 + 1u;
    RND(17) RND(29) RND(16) RND(24)  x0 += k2; x1 += k0 + 2u;
    RND(13) RND(15) RND(26) RND(6)   x0 += k0; x1 += k1 + 3u;
    RND(17) RND(29) RND(16) RND(24)  x0 += k1; x1 += k2 + 4u;
    RND(13) RND(15) RND(26) RND(6)   x0 += k2; x1 += k0 + 5u;
#undef RND
    return x0 ^ x1;   // 32-bit partitionable: xor of the two output words
}

// accurate fp32 ln (immune to -use_fast_math), ~1-2 ulp on [2^-126, 2)
__device__ __forceinline__ float alogf(float x) {
    int i = __float_as_int(x);
    int e = ((i >> 23) & 0xFF) - 127;
    float m = __int_as_float((i & 0x007FFFFF) | 0x3F800000);
    if (m > 1.41421356f) { m *= 0.5f; e += 1; }
    float t = m - 1.0f;
    float s = __fdiv_rn(t, t + 2.0f);
    float z = s * s;
    float poly = fmaf(z, fmaf(z, fmaf(z, 0.14285715f, 0.2f), 0.33333334f), 1.0f);
    float lnm = 2.0f * s * poly;
    float ef = (float)e;
    return fmaf(ef, 0.693359375f, fmaf(ef, -2.12194440e-4f, lnm));
}

__device__ __forceinline__ float neg_log_u(unsigned bits) {
    float u = __uint_as_float((bits >> 9) | 0x3F800000u) - 1.0f;
    u = fmaxf(u, 1.17549435e-38f);   // bitwise-equal to JAX's minval clamp
    return -alogf(u);                // a = -ln u > 0
}

// ---------------- K3: gumbel-bernoulli mask (8 cols/thread) ----------------
// decision: p^2 * a1 >= (1-p)^2 * a0; fp32 fast path + guard band, fp64 fallback.
// per-element arithmetic identical to the 803us version; only thread->work map changed.
__global__ void __launch_bounds__(256) k_mask(float* __restrict__ out) {
    int g = blockIdx.x * blockDim.x + threadIdx.x;   // 2M threads, 8 cols each
    int c0 = (g & 127) << 3;
    int r  = (g >> 7) & 1023;
    int b  = g >> 17;
    size_t rowbase = ((size_t)b * Nn + r) * Nn;
    float4 dvA = *(const float4*)(g_dist + rowbase + c0);
    float4 dvB = *(const float4*)(g_dist + rowbase + c0 + 4);
    float dmin  = __uint_as_float(g_minbits[b * Nn + r]);
    float emax  = __fdiv_rn(1.0f, __fadd_rn(dmin, 1e-10f));
    float emaxp = __fadd_rn(emax, 1e-10f);
    float dd[8] = {dvA.x, dvA.y, dvA.z, dvA.w, dvB.x, dvB.y, dvB.z, dvB.w};
    unsigned lbase = ((unsigned)(b * Nn + r) * (unsigned)Nn + (unsigned)c0) * 2u;
    float res[8];
#pragma unroll
    for (int q = 0; q < 8; q++) {
        int c = c0 + q;
        float p;
        if (c == r) {
            p = 0.01f;
        } else {
            float ed = __fdiv_rn(1.0f, __fadd_rn(dd[q], 1e-10f));
            p = __fmul_rn(__fdiv_rn(ed, emaxp), 0.99f);
        }
        float a0 = neg_log_u(tf_bits(lbase + 2u * (unsigned)q));
        float a1 = neg_log_u(tf_bits(lbase + 2u * (unsigned)q + 1u));
        float om = __fsub_rn(1.0f, p);
        float t1 = __fmul_rn(__fmul_rn(p,  p),  a1);
        float t0 = __fmul_rn(__fmul_rn(om, om), a0);
        float diff = __fsub_rn(t1, t0);
        if (fabsf(diff) > __fmul_rn(4e-7f, __fadd_rn(t1, t0))) {
            res[q] = (diff >= 0.0f) ? 1.0f : 0.0f;   // fp32 sign provably == fp64 sign
        } else {
            double pd = (double)p;
            double omd = 1.0 - pd;
            res[q] = (pd * pd * (double)a1 >= omd * omd * (double)a0) ? 1.0f : 0.0f;
        }
    }
    *(float4*)(out + rowbase + c0)     = make_float4(res[0], res[1], res[2], res[3]);
    *(float4*)(out + rowbase + c0 + 4) = make_float4(res[4], res[5], res[6], res[7]);
}

// ---------------- launch ----------------
extern "C" void kernel_launch(void* const* d_in, const int* in_sizes, int n_in,
                              void* d_out, int out_size) {
    const float* X = (const float*)d_in[0];
    const float* A = (const float*)d_in[1];
    float* out = (float*)d_out;

    k_init<<<64, 256>>>(A);
    k_dft<<<NROW / DFT_ROWS, 288>>>(X);
    dim3 gg(Nn / 128, Nn / 128, Bn);
    k_gram<<<gg, 256>>>();
    k_mask<<<(Bn * Nn * (Nn / 8)) / 256, 256>>>(out);
}

// round 16
// speedup vs baseline: 1.6124x; 1.0481x over previous
#include <cuda_runtime.h>
#include <cstdint>

#define Bn 16
#define Nn 1024
#define Dn 512
#define Fn 257
#define FP 272            // padded to multiple of 16 for gram k-chunks
#define NROW (Bn*Nn)

// ---------------- scratch (static device globals; no allocation) ----------------
__device__ float    g_w[FP];
__device__ float    g_twg[512];                    // (float)cos(2pi k/512), filled once
__device__ float    g_Y[(size_t)NROW * FP];        // ~17.8 MB
__device__ float    g_sq[NROW];
__device__ unsigned g_minbits[NROW];               // float bits of row-min dist (j != i)
__device__ float    g_dist[(size_t)NROW * Nn];     // 64 MB

// ---------------- exact-rounding helper (DFT only) ----------------
__device__ __forceinline__ void two_sum(float a, float b, float& s, float& e) {
    s = __fadd_rn(a, b);
    float bb = __fsub_rn(s, a);
    e = __fadd_rn(__fsub_rn(a, __fsub_rn(s, bb)), __fsub_rn(b, bb));
}

// ---------------- K0: w = rowsum(A); twiddle table; init row mins ----------------
__global__ void k_init(const float* __restrict__ A) {
    int t = blockIdx.x * blockDim.x + threadIdx.x;
    if (t < NROW) g_minbits[t] = 0x7F800000u;  // +inf
    if (t < 512) {
        double ang = (2.0 * 3.141592653589793238 / 512.0) * (double)t;
        g_twg[t] = (float)cos(ang);            // same value bits as before
    }
    int w = t >> 5, lane = t & 31;
    if (w < FP) {
        float s = 0.f;
        if (w < Fn) {
            for (int j = lane; j < Fn; j += 32) s = __fadd_rn(s, A[w * Fn + j]);
        }
#pragma unroll
        for (int o = 16; o; o >>= 1) s = __fadd_rn(s, __shfl_down_sync(0xFFFFFFFFu, s, o));
        if (lane == 0) g_w[w] = s;   // padded rows (w>=Fn) write 0
    }
}

// ---------------- K1: Y[row][f] = |DFT_f(x_row)| * w[f], compensated ----------------
// round-11 version verbatim (best measured)
#define DFT_ROWS 4
__global__ void __launch_bounds__(288) k_dft(const float* __restrict__ X) {
    __shared__ float tw[512];
    __shared__ float xs[DFT_ROWS][512];
    int tid = threadIdx.x;
    for (int k = tid; k < 512; k += 288) tw[k] = g_twg[k];
    int row0 = blockIdx.x * DFT_ROWS;
    const float* Xp = X + (size_t)row0 * Dn;
    for (int i = tid; i < DFT_ROWS * Dn; i += 288) xs[i >> 9][i & 511] = Xp[i];
    __syncthreads();

    int f = tid;
    if (f < Fn) {
        float rs[DFT_ROWS], re_[DFT_ROWS], is_[DFT_ROWS], ie_[DFT_ROWS];
#pragma unroll
        for (int r = 0; r < DFT_ROWS; r++) { rs[r] = 0.f; re_[r] = 0.f; is_[r] = 0.f; ie_[r] = 0.f; }
        int k = 0;
        for (int ch = 0; ch < 32; ch++) {            // 32 chunks of 16 samples
            float rc[DFT_ROWS], ic[DFT_ROWS];
#pragma unroll
            for (int r = 0; r < DFT_ROWS; r++) { rc[r] = 0.f; ic[r] = 0.f; }
#pragma unroll
            for (int d4 = 0; d4 < 4; d4++) {
                int dbase = ch * 16 + d4 * 4;
                float4 xv[DFT_ROWS];
#pragma unroll
                for (int r = 0; r < DFT_ROWS; r++) xv[r] = *(const float4*)&xs[r][dbase];
#pragma unroll
                for (int dd = 0; dd < 4; dd++) {
                    float c = tw[k];
                    float s = tw[(k + 128) & 511];   // == -sin (sign irrelevant for |.|)
#pragma unroll
                    for (int r = 0; r < DFT_ROWS; r++) {
                        float x = (dd == 0) ? xv[r].x : (dd == 1) ? xv[r].y : (dd == 2) ? xv[r].z : xv[r].w;
                        rc[r] = fmaf(x, c, rc[r]);
                        ic[r] = fmaf(x, s, ic[r]);
                    }
                    k = (k + f) & 511;
                }
            }
            // TwoSum-fold chunk partials into compensated accumulators
#pragma unroll
            for (int r = 0; r < DFT_ROWS; r++) {
                float s, e;
                two_sum(rs[r], rc[r], s, e);  rs[r]  = s; re_[r] = __fadd_rn(re_[r], e);
                two_sum(is_[r], ic[r], s, e); is_[r] = s; ie_[r] = __fadd_rn(ie_[r], e);
            }
        }
        float wf = g_w[f];
#pragma unroll
        for (int r = 0; r < DFT_ROWS; r++) {
            // float-float magnitude: (rs+re)^2 + (is+ie)^2, refined sqrt
            float hr = __fmul_rn(rs[r], rs[r]);
            float lr = fmaf(rs[r], rs[r], -hr);
            float hi = __fmul_rn(is_[r], is_[r]);
            float li = fmaf(is_[r], is_[r], -hi);
            float S, E;
            two_sum(hr, hi, S, E);
            float cross2 = __fadd_rn(__fmul_rn(2.0f, __fmul_rn(rs[r], re_[r])),
                                     __fmul_rn(2.0f, __fmul_rn(is_[r], ie_[r])));
            E = __fadd_rn(E, __fadd_rn(__fadd_rn(lr, li), cross2));
            float rt = __fsqrt_rn(S);
            float resid = __fadd_rn(fmaf(-rt, rt, S), E);
            float mag = fmaf(resid, __fdiv_rn(0.5f, rt), rt);
            if (S == 0.0f) mag = 0.0f;
            g_Y[(size_t)(row0 + r) * FP + f] = __fmul_rn(mag, wf);
        }
    } else if (f < FP) {
        for (int r = 0; r < DFT_ROWS; r++) g_Y[(size_t)(row0 + r) * FP + f] = 0.f;
    }
}

// ---------------- K1b: sq[row] = sum_f Y^2 — XLA row-reduce mimicry ----------------
__global__ void __launch_bounds__(256) k_sq() {
    int row = blockIdx.x * 8 + (threadIdx.x >> 5);
    int lane = threadIdx.x & 31;
    const float* Yp = g_Y + (size_t)row * FP;
    float s = 0.f;
    for (int f = lane; f < Fn; f += 32) {
        float y = Yp[f];
        s = __fadd_rn(s, __fmul_rn(y, y));   // mul then add, NOT fma
    }
#pragma unroll
    for (int o = 16; o; o >>= 1) s = __fadd_rn(s, __shfl_down_sync(0xFFFFFFFFu, s, o));
    if (lane == 0) g_sq[row] = s;
}

// ---------------- K2: Gram -> dist + row-min (scalar version, at FFMA roofline) -----
__global__ void __launch_bounds__(256) k_gram() {
    __shared__ float As[16][132];
    __shared__ float Bs[16][132];
    int b = blockIdx.z;
    int i0 = blockIdx.y * 128, j0 = blockIdx.x * 128;
    const float* Yb = g_Y + (size_t)b * Nn * FP;
    int tid = threadIdx.x;
    int tx = tid & 15, ty = tid >> 4;
    float acc[8][8];
#pragma unroll
    for (int q = 0; q < 8; q++)
#pragma unroll
        for (int w = 0; w < 8; w++) acc[q][w] = 0.f;

    for (int k0 = 0; k0 < FP; k0 += 16) {
#pragma unroll
        for (int q = 0; q < 2; q++) {
            int idx = tid + q * 256;       // 0..511
            int i   = idx >> 2;            // tile row 0..127
            int k4  = (idx & 3) << 2;      // 0,4,8,12
            float4 va = *(const float4*)&Yb[(size_t)(i0 + i) * FP + k0 + k4];
            As[k4 + 0][i] = va.x; As[k4 + 1][i] = va.y; As[k4 + 2][i] = va.z; As[k4 + 3][i] = va.w;
            float4 vb = *(const float4*)&Yb[(size_t)(j0 + i) * FP + k0 + k4];
            Bs[k4 + 0][i] = vb.x; Bs[k4 + 1][i] = vb.y; Bs[k4 + 2][i] = vb.z; Bs[k4 + 3][i] = vb.w;
        }
        __syncthreads();
#pragma unroll
        for (int kk = 0; kk < 16; kk++) {
            float av[8], bw[8];
            *(float4*)&av[0] = *(const float4*)&As[kk][ty * 8];
            *(float4*)&av[4] = *(const float4*)&As[kk][ty * 8 + 4];
            *(float4*)&bw[0] = *(const float4*)&Bs[kk][tx * 8];
            *(float4*)&bw[4] = *(const float4*)&Bs[kk][tx * 8 + 4];
#pragma unroll
            for (int q = 0; q < 8; q++)
#pragma unroll
                for (int w = 0; w < 8; w++) acc[q][w] = fmaf(av[q], bw[w], acc[q][w]);
        }
        __syncthreads();
    }

    float sqi[8], sqj[8], rmin[8];
#pragma unroll
    for (int q = 0; q < 8; q++) { sqi[q] = g_sq[b * Nn + i0 + ty * 8 + q]; rmin[q] = 3.0e38f; }
#pragma unroll
    for (int w = 0; w < 8; w++) sqj[w] = g_sq[b * Nn + j0 + tx * 8 + w];

    float* distp = g_dist + (size_t)b * Nn * Nn;
#pragma unroll
    for (int q = 0; q < 8; q++) {
        int i = i0 + ty * 8 + q;
        float dl[8];
#pragma unroll
        for (int w = 0; w < 8; w++) {
            int j = j0 + tx * 8 + w;
            // ref op order: (sq_i + sq_j) - 2*cross, then max(.,0), no FMA
            float t = __fadd_rn(sqi[q], sqj[w]);
            float d = fmaxf(__fsub_rn(t, __fmul_rn(2.0f, acc[q][w])), 0.f);
            dl[w] = d;
            if (i != j) rmin[q] = fminf(rmin[q], d);
        }
        *(float4*)(distp + (size_t)i * Nn + j0 + tx * 8)     = make_float4(dl[0], dl[1], dl[2], dl[3]);
        *(float4*)(distp + (size_t)i * Nn + j0 + tx * 8 + 4) = make_float4(dl[4], dl[5], dl[6], dl[7]);
    }
#pragma unroll
    for (int q = 0; q < 8; q++) {
        float m = rmin[q];
#pragma unroll
        for (int o = 8; o; o >>= 1) m = fminf(m, __shfl_down_sync(0xFFFFFFFFu, m, o, 16));
        if (tx == 0) atomicMin(&g_minbits[b * Nn + i0 + ty * 8 + q], __float_as_uint(m));
    }
}

// ---------------- threefry2x32 (JAX partitionable random_bits, 32-bit) ----------------
__device__ __forceinline__ unsigned tf_bits(unsigned lo) {
    const unsigned k0 = 0u, k1 = 42u, k2 = 0x1BD11BDAu ^ 0u ^ 42u;
    unsigned x0 = 0u + k0;      // hi32 of uint64 iota index is 0 for this size
    unsigned x1 = lo + k1;
#define RND(r) { x0 += x1; x1 = __funnelshift_l(x1, x1, (r)); x1 ^= x0; }
    RND(13) RND(15) RND(26) RND(6)   x0 += k1; x1 += k2 + 1u;
    RND(17) RND(29) RND(16) RND(24)  x0 += k2; x1 += k0 + 2u;
    RND(13) RND(15) RND(26) RND(6)   x0 += k0; x1 += k1 + 3u;
    RND(17) RND(29) RND(16) RND(24)  x0 += k1; x1 += k2 + 4u;
    RND(13) RND(15) RND(26) RND(6)   x0 += k2; x1 += k0 + 5u;
#undef RND
    return x0 ^ x1;   // 32-bit partitionable: xor of the two output words
}

// accurate fp32 ln (immune to -use_fast_math), ~1-2 ulp on [2^-126, 2)
__device__ __forceinline__ float alogf(float x) {
    int i = __float_as_int(x);
    int e = ((i >> 23) & 0xFF) - 127;
    float m = __int_as_float((i & 0x007FFFFF) | 0x3F800000);
    if (m > 1.41421356f) { m *= 0.5f; e += 1; }
    float t = m - 1.0f;
    float s = __fdiv_rn(t, t + 2.0f);
    float z = s * s;
    float poly = fmaf(z, fmaf(z, fmaf(z, 0.14285715f, 0.2f), 0.33333334f), 1.0f);
    float lnm = 2.0f * s * poly;
    float ef = (float)e;
    return fmaf(ef, 0.693359375f, fmaf(ef, -2.12194440e-4f, lnm));
}

__device__ __forceinline__ float neg_log_u(unsigned bits) {
    float u = __uint_as_float((bits >> 9) | 0x3F800000u) - 1.0f;
    u = fmaxf(u, 1.17549435e-38f);   // bitwise-equal to JAX's minval clamp
    return -alogf(u);                // a = -ln u > 0
}

// ---------------- K3: gumbel-bernoulli mask (8 cols/thread, measured 134us) --------
// decision: p^2 * a1 >= (1-p)^2 * a0; fp32 fast path + guard band, fp64 fallback.
__global__ void __launch_bounds__(256) k_mask(float* __restrict__ out) {
    int g = blockIdx.x * blockDim.x + threadIdx.x;   // 2M threads, 8 cols each
    int c0 = (g & 127) << 3;
    int r  = (g >> 7) & 1023;
    int b  = g >> 17;
    size_t rowbase = ((size_t)b * Nn + r) * Nn;
    float4 dvA = *(const float4*)(g_dist + rowbase + c0);
    float4 dvB = *(const float4*)(g_dist + rowbase + c0 + 4);
    float dmin  = __uint_as_float(g_minbits[b * Nn + r]);
    float emax  = __fdiv_rn(1.0f, __fadd_rn(dmin, 1e-10f));
    float emaxp = __fadd_rn(emax, 1e-10f);
    float dd[8] = {dvA.x, dvA.y, dvA.z, dvA.w, dvB.x, dvB.y, dvB.z, dvB.w};
    unsigned lbase = ((unsigned)(b * Nn + r) * (unsigned)Nn + (unsigned)c0) * 2u;
    float res[8];
#pragma unroll
    for (int q = 0; q < 8; q++) {
        int c = c0 + q;
        float p;
        if (c == r) {
            p = 0.01f;
        } else {
            float ed = __fdiv_rn(1.0f, __fadd_rn(dd[q], 1e-10f));
            p = __fmul_rn(__fdiv_rn(ed, emaxp), 0.99f);
        }
        float a0 = neg_log_u(tf_bits(lbase + 2u * (unsigned)q));
        float a1 = neg_log_u(tf_bits(lbase + 2u * (unsigned)q + 1u));
        float om = __fsub_rn(1.0f, p);
        float t1 = __fmul_rn(__fmul_rn(p,  p),  a1);
        float t0 = __fmul_rn(__fmul_rn(om, om), a0);
        float diff = __fsub_rn(t1, t0);
        if (fabsf(diff) > __fmul_rn(4e-7f, __fadd_rn(t1, t0))) {
            res[q] = (diff >= 0.0f) ? 1.0f : 0.0f;   // fp32 sign provably == fp64 sign
        } else {
            double pd = (double)p;
            double omd = 1.0 - pd;
            res[q] = (pd * pd * (double)a1 >= omd * omd * (double)a0) ? 1.0f : 0.0f;
        }
    }
    *(float4*)(out + rowbase + c0)     = make_float4(res[0], res[1], res[2], res[3]);
    *(float4*)(out + rowbase + c0 + 4) = make_float4(res[4], res[5], res[6], res[7]);
}

// ---------------- launch ----------------
extern "C" void kernel_launch(void* const* d_in, const int* in_sizes, int n_in,
                              void* d_out, int out_size) {
    const float* X = (const float*)d_in[0];
    const float* A = (const float*)d_in[1];
    float* out = (float*)d_out;

    k_init<<<64, 256>>>(A);
    k_dft<<<NROW / DFT_ROWS, 288>>>(X);
    k_sq<<<NROW / 8, 256>>>();
    dim3 gg(Nn / 128, Nn / 128, Bn);
    k_gram<<<gg, 256>>>();
    k_mask<<<(Bn * Nn * (Nn / 8)) / 256, 256>>>(out);
}